// round 2
// baseline (speedup 1.0000x reference)
#include <cuda_runtime.h>
#include <cstdint>

#define DIM      4096
#define NPAIRS   2048
#define GRD      64
#define P_TILE   4
#define THREADS  1024
#define BSTEP    (THREADS / P_TILE)          // 256
#define GRID_ELEMS (GRD * GRD)               // 4096 floats per pair
#define SMEM_BYTES (P_TILE * GRID_ELEMS * 4) // 64 KB

__global__ void __launch_bounds__(THREADS, 2)
pair_bilinear_kernel(const float* __restrict__ x,
                     const float* __restrict__ pairW,
                     const float* __restrict__ Y,
                     float* __restrict__ out,
                     int batch, int b_tile)
{
    extern __shared__ float sY[];  // P_TILE * 64 * 64 floats = 64 KB

    const int p0 = blockIdx.x * P_TILE;

    // Stage P_TILE grids of Y into shared memory (bulk, coalesced float4)
    {
        const float4* __restrict__ Yg = reinterpret_cast<const float4*>(Y) + p0 * (GRID_ELEMS / 4);
        float4* sY4 = reinterpret_cast<float4*>(sY);
        #pragma unroll
        for (int i = threadIdx.x; i < P_TILE * GRID_ELEMS / 4; i += THREADS)
            sY4[i] = Yg[i];
    }
    __syncthreads();

    const int pl = threadIdx.x & (P_TILE - 1);   // pair within tile (0..3)
    const int bs = threadIdx.x >> 2;             // batch sub-index (0..255)
    const int p  = p0 + pl;

    // Per-pair 2x2 weights live in registers for the whole loop
    const float4 w = *(reinterpret_cast<const float4*>(pairW) + p);
    // w.x = W[0][0], w.y = W[0][1], w.z = W[1][0], w.w = W[1][1]

    const float* __restrict__ sYp = sY + pl * GRID_ELEMS;

    const int bstart = blockIdx.y * b_tile + bs;
    const int bend   = min(blockIdx.y * b_tile + b_tile, batch);

    // 32-bit pointer-increment addressing (keep register count <= 32)
    const float2* __restrict__ xp_ptr =
        reinterpret_cast<const float2*>(x + bstart * DIM) + p;
    float* __restrict__ op = out + bstart * NPAIRS + p;

    #pragma unroll 2
    for (int b = bstart; b < bend; b += BSTEP) {
        const float2 xv = *xp_ptr;
        xp_ptr += BSTEP * (DIM / 2);

        // xp[j] = x0 * W[0][j] + x1 * W[1][j]
        const float xp0 = fmaf(xv.x, w.x, xv.y * w.z);
        const float xp1 = fmaf(xv.x, w.y, xv.y * w.w);

        const float g0 = fminf(fmaxf(xp0 * 63.0f, 0.0f), 63.0f);
        const float g1 = fminf(fmaxf(xp1 * 63.0f, 0.0f), 63.0f);

        const int r0 = min((int)g0, 62);   // g >= 0, trunc == floor
        const int c0 = min((int)g1, 62);
        const float fr = g0 - (float)r0;
        const float fc = g1 - (float)c0;

        const float* __restrict__ cell = sYp + (r0 << 6) + c0;
        const float y00 = cell[0];
        const float y01 = cell[1];
        const float y10 = cell[GRD];
        const float y11 = cell[GRD + 1];

        const float top = fmaf(fc, y01 - y00, y00);
        const float bot = fmaf(fc, y11 - y10, y10);
        *op = fmaf(fr, bot - top, top);
        op += BSTEP * NPAIRS;
    }
}

extern "C" void kernel_launch(void* const* d_in, const int* in_sizes, int n_in,
                              void* d_out, int out_size)
{
    const float* x     = (const float*)d_in[0];
    const float* pairW = (const float*)d_in[1];
    const float* Y     = (const float*)d_in[2];
    float* out         = (float*)d_out;

    const int batch = in_sizes[0] / DIM;   // 8192

    const int b_blocks = 4;
    const int b_tile = (batch + b_blocks - 1) / b_blocks;

    cudaFuncSetAttribute(pair_bilinear_kernel,
                         cudaFuncAttributeMaxDynamicSharedMemorySize, SMEM_BYTES);

    dim3 grid(NPAIRS / P_TILE, b_blocks);   // (512, 4) = 2048 blocks
    pair_bilinear_kernel<<<grid, THREADS, SMEM_BYTES>>>(x, pairW, Y, out, batch, b_tile);
}

// round 3
// speedup vs baseline: 1.2291x; 1.2291x over previous
#include <cuda_runtime.h>
#include <cuda_fp16.h>
#include <cstdint>

#define DIM      4096
#define NPAIRS   2048
#define GRD      64
#define P_TILE   8
#define THREADS  1024
#define BSTEP    (THREADS / P_TILE)             // 128
#define GRID_ELEMS (GRD * GRD)                  // 4096 cells per pair
#define SMEM_BYTES (P_TILE * GRID_ELEMS * 4)    // 128 KB (half2 cells)

__global__ void __launch_bounds__(THREADS, 1)
pair_bilinear_kernel(const float* __restrict__ x,
                     const float* __restrict__ pairW,
                     const float* __restrict__ Y,
                     float* __restrict__ out,
                     int batch, int b_tile)
{
    extern __shared__ __half2 sY[];  // [P_TILE][64][64] : cell = {Y[r][c], Y[r][c+1]}

    const int p0 = blockIdx.x * P_TILE;

    // ── Stage: build duplicated-pair fp16 grid from fp32 Y ────────────────
    // Process 4 cells per thread from one float4. Cell c+3's second element
    // uses v.w as a dummy when it would cross the float4 (cell 63 is never
    // read in the main loop since c0 <= 62, and for c%4 interior cells the
    // true neighbor is inside the float4).
    {
        const float4* __restrict__ Yg =
            reinterpret_cast<const float4*>(Y) + p0 * (GRID_ELEMS / 4);
        #pragma unroll
        for (int i = threadIdx.x; i < P_TILE * GRID_ELEMS / 4; i += THREADS) {
            const float4 v = Yg[i];
            __half2* d = sY + i * 4;
            d[0] = __floats2half2_rn(v.x, v.y);
            d[1] = __floats2half2_rn(v.y, v.z);
            d[2] = __floats2half2_rn(v.z, v.w);
            d[3] = __floats2half2_rn(v.w, v.w);   // cell (c%4)==3: neighbor is
                                                  // next float4; only cell 63
                                                  // truly lacks it & is unread.
        }
        // Fix the 3-of-4 cells whose neighbor lives in the next float4:
        // cells with c % 4 == 3 and c < 63 need Y[r][c+1].
        #pragma unroll
        for (int i = threadIdx.x; i < P_TILE * GRID_ELEMS / 4; i += THREADS) {
            const int c4 = (i & 15);              // float4 index within row (0..15)
            if (c4 < 15) {
                const float vnext = *(reinterpret_cast<const float*>(Yg + i + 1));
                const float vlast = reinterpret_cast<const float*>(Yg + i)[3];
                sY[i * 4 + 3] = __floats2half2_rn(vlast, vnext);
            }
        }
    }
    __syncthreads();

    const int pl = threadIdx.x & (P_TILE - 1);   // pair within tile (0..7)
    const int bs = threadIdx.x >> 3;             // batch sub-index (0..127)
    const int p  = p0 + pl;

    const float4 w = *(reinterpret_cast<const float4*>(pairW) + p);
    // w.x=W00, w.y=W01, w.z=W10, w.w=W11

    const __half2* __restrict__ sYp = sY + pl * GRID_ELEMS;

    const int bstart = blockIdx.y * b_tile + bs;
    const int bend   = min(blockIdx.y * b_tile + b_tile, batch);

    const float2* __restrict__ xp_ptr =
        reinterpret_cast<const float2*>(x + bstart * DIM) + p;
    float* __restrict__ op = out + bstart * NPAIRS + p;

    #pragma unroll 8
    for (int b = bstart; b < bend; b += BSTEP) {
        const float2 xv = *xp_ptr;
        xp_ptr += BSTEP * (DIM / 2);

        const float xp0 = fmaf(xv.x, w.x, xv.y * w.z);
        const float xp1 = fmaf(xv.x, w.y, xv.y * w.w);

        const float g0 = fminf(fmaxf(xp0 * 63.0f, 0.0f), 63.0f);
        const float g1 = fminf(fmaxf(xp1 * 63.0f, 0.0f), 63.0f);

        const int r0 = min((int)g0, 62);
        const int c0 = min((int)g1, 62);
        const float fr = g0 - (float)r0;
        const float fc = g1 - (float)c0;

        const int base = (r0 << 6) + c0;
        const float2 top2 = __half22float2(sYp[base]);        // {y00, y01}
        const float2 bot2 = __half22float2(sYp[base + GRD]);  // {y10, y11}

        const float top = fmaf(fc, top2.y - top2.x, top2.x);
        const float bot = fmaf(fc, bot2.y - bot2.x, bot2.x);
        *op = fmaf(fr, bot - top, top);
        op += BSTEP * NPAIRS;
    }
}

extern "C" void kernel_launch(void* const* d_in, const int* in_sizes, int n_in,
                              void* d_out, int out_size)
{
    const float* x     = (const float*)d_in[0];
    const float* pairW = (const float*)d_in[1];
    const float* Y     = (const float*)d_in[2];
    float* out         = (float*)d_out;

    const int batch = in_sizes[0] / DIM;   // 8192

    const int b_blocks = 4;
    const int b_tile = (batch + b_blocks - 1) / b_blocks;

    cudaFuncSetAttribute(pair_bilinear_kernel,
                         cudaFuncAttributeMaxDynamicSharedMemorySize, SMEM_BYTES);

    dim3 grid(NPAIRS / P_TILE, b_blocks);   // (256, 4) = 1024 blocks
    pair_bilinear_kernel<<<grid, THREADS, SMEM_BYTES>>>(x, pairW, Y, out, batch, b_tile);
}

// round 4
// speedup vs baseline: 1.2835x; 1.0443x over previous
#include <cuda_runtime.h>
#include <cuda_fp16.h>
#include <cstdint>

#define DIM      4096
#define NPAIRS   2048
#define GRD      64
#define P_TILE   8
#define THREADS  1024
#define BSTEP    (THREADS / P_TILE)             // 128
#define GRID_ELEMS (GRD * GRD)                  // 4096 cells per pair
#define SMEM_BYTES (P_TILE * GRID_ELEMS * 4)    // 128 KB (half2 cells)
#define GSIZE    4                              // iterations per pipeline group
#define XSTRIDE  (BSTEP * (DIM / 2))            // float2 elements per iter step
#define OSTRIDE  (BSTEP * NPAIRS)               // float elements per iter step

__global__ void __launch_bounds__(THREADS, 1)
pair_bilinear_kernel(const float* __restrict__ x,
                     const float* __restrict__ pairW,
                     const float* __restrict__ Y,
                     float* __restrict__ out,
                     int b_tile, int groups)
{
    extern __shared__ __half2 sY[];  // [P_TILE][64][64] : cell = {Y[r][c], Y[r][c+1]}

    const int p0 = blockIdx.x * P_TILE;

    // ── Stage: duplicated-pair fp16 grid from fp32 Y (single pass) ────────
    {
        const float4* __restrict__ Yg =
            reinterpret_cast<const float4*>(Y) + p0 * (GRID_ELEMS / 4);
        #pragma unroll
        for (int i = threadIdx.x; i < P_TILE * GRID_ELEMS / 4; i += THREADS) {
            const float4 v = Yg[i];
            const int c4 = i & 15;               // float4 index within 64-wide row
            // neighbor of v.w lives in the next float4 (cell 63 never read)
            const float vnext = (c4 < 15) ? *reinterpret_cast<const float*>(Yg + i + 1)
                                          : v.w;
            __half2* d = sY + i * 4;
            d[0] = __floats2half2_rn(v.x, v.y);
            d[1] = __floats2half2_rn(v.y, v.z);
            d[2] = __floats2half2_rn(v.z, v.w);
            d[3] = __floats2half2_rn(v.w, vnext);
        }
    }
    __syncthreads();

    const int pl = threadIdx.x & (P_TILE - 1);   // pair within tile (0..7)
    const int bs = threadIdx.x >> 3;             // batch sub-index (0..127)
    const int p  = p0 + pl;

    const float4 w = *(reinterpret_cast<const float4*>(pairW) + p);
    // w.x=W00, w.y=W01, w.z=W10, w.w=W11

    const __half2* __restrict__ sYp = sY + pl * GRID_ELEMS;

    const int bstart = blockIdx.y * b_tile + bs;

    const float2* __restrict__ xp =
        reinterpret_cast<const float2*>(x + bstart * DIM) + p;
    float* __restrict__ op = out + bstart * NPAIRS + p;

    // ── Software-pipelined main loop: prefetch x one group ahead;
    //    per group, issue all 8 LDS before any consumes. ──────────────────
    float2 xa[GSIZE];
    #pragma unroll
    for (int i = 0; i < GSIZE; i++) xa[i] = xp[i * XSTRIDE];
    xp += GSIZE * XSTRIDE;

    for (int gset = 0; gset < groups; ++gset) {
        float2 xb[GSIZE];
        if (gset + 1 < groups) {
            #pragma unroll
            for (int i = 0; i < GSIZE; i++) xb[i] = xp[i * XSTRIDE];
            xp += GSIZE * XSTRIDE;
        }

        __half2 t2[GSIZE], b2[GSIZE];
        float fr[GSIZE], fc[GSIZE];

        // Phase A: addresses + all gathers in flight
        #pragma unroll
        for (int i = 0; i < GSIZE; i++) {
            const float xp0 = fmaf(xa[i].x, w.x, xa[i].y * w.z);
            const float xp1 = fmaf(xa[i].x, w.y, xa[i].y * w.w);
            const float g0 = fminf(fmaxf(xp0 * 63.0f, 0.0f), 63.0f);
            const float g1 = fminf(fmaxf(xp1 * 63.0f, 0.0f), 63.0f);
            const int r0 = min((int)g0, 62);
            const int c0 = min((int)g1, 62);
            fr[i] = g0 - (float)r0;
            fc[i] = g1 - (float)c0;
            const int base = (r0 << 6) + c0;
            t2[i] = sYp[base];
            b2[i] = sYp[base + GRD];
        }

        // Phase B: blend + store
        #pragma unroll
        for (int i = 0; i < GSIZE; i++) {
            const float2 t = __half22float2(t2[i]);
            const float2 b = __half22float2(b2[i]);
            const float top = fmaf(fc[i], t.y - t.x, t.x);
            const float bot = fmaf(fc[i], b.y - b.x, b.x);
            *op = fmaf(fr[i], bot - top, top);
            op += OSTRIDE;
        }

        #pragma unroll
        for (int i = 0; i < GSIZE; i++) xa[i] = xb[i];
    }
}

extern "C" void kernel_launch(void* const* d_in, const int* in_sizes, int n_in,
                              void* d_out, int out_size)
{
    const float* x     = (const float*)d_in[0];
    const float* pairW = (const float*)d_in[1];
    const float* Y     = (const float*)d_in[2];
    float* out         = (float*)d_out;

    const int batch = in_sizes[0] / DIM;   // 8192

    const int b_blocks = 4;
    const int b_tile = batch / b_blocks;               // 2048
    const int groups = b_tile / (GSIZE * BSTEP);       // 4 (exact: 8192 % 2048 == 0)

    cudaFuncSetAttribute(pair_bilinear_kernel,
                         cudaFuncAttributeMaxDynamicSharedMemorySize, SMEM_BYTES);

    dim3 grid(NPAIRS / P_TILE, b_blocks);   // (256, 4) = 1024 blocks
    pair_bilinear_kernel<<<grid, THREADS, SMEM_BYTES>>>(x, pairW, Y, out, b_tile, groups);
}

// round 6
// speedup vs baseline: 1.3147x; 1.0243x over previous
#include <cuda_runtime.h>
#include <cuda_fp16.h>
#include <cstdint>

#define DIM      4096
#define NPAIRS   2048
#define GRD      64
#define P_TILE   8                               // pairs staged per block
#define THREADS  1024
#define SLOTS    4                               // pair-slots (2 pairs each)
#define BSTEP    (THREADS / SLOTS)               // 256 batch rows per iter
#define GRID_ELEMS (GRD * GRD)                   // 4096 cells per pair
#define SMEM_BYTES (P_TILE * GRID_ELEMS * 4)     // 128 KB (half2 dup-pair cells)
#define GSIZE    2                               // iterations per pipeline group

__global__ void __launch_bounds__(THREADS, 1)
pair_bilinear_kernel(const float* __restrict__ x,
                     const float* __restrict__ pairW,
                     const float* __restrict__ Y,
                     float* __restrict__ out,
                     int b_tile, int groups)
{
    extern __shared__ __half2 sY[];  // [P_TILE][64][64] : cell = {Y[r][c], Y[r][c+1]}

    const int p0 = blockIdx.x * P_TILE;

    // ── Stage: duplicated-pair fp16 grid from fp32 Y, vectorized stores ──
    {
        const float4* __restrict__ Yg =
            reinterpret_cast<const float4*>(Y) + p0 * (GRID_ELEMS / 4);
        uint4* __restrict__ sY4 = reinterpret_cast<uint4*>(sY);
        #pragma unroll
        for (int i = threadIdx.x; i < P_TILE * GRID_ELEMS / 4; i += THREADS) {
            const float4 v = Yg[i];
            const int c4 = i & 15;               // float4 index within 64-wide row
            const float vnext = (c4 < 15) ? *reinterpret_cast<const float*>(Yg + i + 1)
                                          : v.w;  // cell 63 never read
            __half2 h[4];
            h[0] = __floats2half2_rn(v.x, v.y);
            h[1] = __floats2half2_rn(v.y, v.z);
            h[2] = __floats2half2_rn(v.z, v.w);
            h[3] = __floats2half2_rn(v.w, vnext);
            sY4[i] = *reinterpret_cast<const uint4*>(h);   // STS.128, conflict-free
        }
    }
    __syncthreads();

    const int sl = threadIdx.x & (SLOTS - 1);    // pair-slot (0..3) -> pairs 2sl,2sl+1
    const int bs = threadIdx.x >> 2;             // batch sub-index (0..255)
    const int pA = p0 + 2 * sl;                  // first pair of this thread

    const float4 wA = *(reinterpret_cast<const float4*>(pairW) + pA);
    const float4 wB = *(reinterpret_cast<const float4*>(pairW) + pA + 1);

    const __half2* __restrict__ sA = sY + (2 * sl) * GRID_ELEMS;
    const __half2* __restrict__ sB = sA + GRID_ELEMS;

    const int bstart = blockIdx.y * b_tile + bs;

    // x: 4 consecutive floats per (b, slot) -> one float4
    const float4* __restrict__ xp =
        reinterpret_cast<const float4*>(x) + bstart * (DIM / 4) + (pA >> 1);
    float2* __restrict__ op =
        reinterpret_cast<float2*>(out + bstart * NPAIRS + pA);

    const int XSTR = BSTEP * (DIM / 4);
    const int OSTR = BSTEP * (NPAIRS / 2);

    // ── Software-pipelined main loop ──────────────────────────────────────
    float4 xa[GSIZE];
    #pragma unroll
    for (int i = 0; i < GSIZE; i++) xa[i] = xp[i * XSTR];
    xp += GSIZE * XSTR;

    for (int gset = 0; gset < groups; ++gset) {
        float4 xb[GSIZE];
        if (gset + 1 < groups) {
            #pragma unroll
            for (int i = 0; i < GSIZE; i++) xb[i] = xp[i * XSTR];
            xp += GSIZE * XSTR;
        }

        __half2 tA[GSIZE], bA[GSIZE], tB[GSIZE], bB[GSIZE];
        float frA[GSIZE], fcA[GSIZE], frB[GSIZE], fcB[GSIZE];

        // Phase A: addresses + all 4*GSIZE gathers in flight
        #pragma unroll
        for (int i = 0; i < GSIZE; i++) {
            // pair A uses (x.x, x.y), pair B uses (x.z, x.w)
            const float a0 = fmaf(xa[i].x, wA.x, xa[i].y * wA.z);
            const float a1 = fmaf(xa[i].x, wA.y, xa[i].y * wA.w);
            const float b0 = fmaf(xa[i].z, wB.x, xa[i].w * wB.z);
            const float b1 = fmaf(xa[i].z, wB.y, xa[i].w * wB.w);

            const float gA0 = fminf(fmaxf(a0 * 63.0f, 0.0f), 63.0f);
            const float gA1 = fminf(fmaxf(a1 * 63.0f, 0.0f), 63.0f);
            const float gB0 = fminf(fmaxf(b0 * 63.0f, 0.0f), 63.0f);
            const float gB1 = fminf(fmaxf(b1 * 63.0f, 0.0f), 63.0f);

            const int rA = min((int)gA0, 62), cA = min((int)gA1, 62);
            const int rB = min((int)gB0, 62), cB = min((int)gB1, 62);
            frA[i] = gA0 - (float)rA;  fcA[i] = gA1 - (float)cA;
            frB[i] = gB0 - (float)rB;  fcB[i] = gB1 - (float)cB;

            const int baseA = (rA << 6) + cA;
            const int baseB = (rB << 6) + cB;
            tA[i] = sA[baseA];  bA[i] = sA[baseA + GRD];
            tB[i] = sB[baseB];  bB[i] = sB[baseB + GRD];
        }

        // Phase B: blend + vectorized store
        #pragma unroll
        for (int i = 0; i < GSIZE; i++) {
            const float2 ta = __half22float2(tA[i]);
            const float2 ba = __half22float2(bA[i]);
            const float2 tb = __half22float2(tB[i]);
            const float2 bb = __half22float2(bB[i]);

            const float topA = fmaf(fcA[i], ta.y - ta.x, ta.x);
            const float botA = fmaf(fcA[i], ba.y - ba.x, ba.x);
            const float topB = fmaf(fcB[i], tb.y - tb.x, tb.x);
            const float botB = fmaf(fcB[i], bb.y - bb.x, bb.x);

            float2 o;
            o.x = fmaf(frA[i], botA - topA, topA);
            o.y = fmaf(frB[i], botB - topB, topB);
            *op = o;                             // STG.64
            op += OSTR;
        }

        #pragma unroll
        for (int i = 0; i < GSIZE; i++) xa[i] = xb[i];
    }
}

extern "C" void kernel_launch(void* const* d_in, const int* in_sizes, int n_in,
                              void* d_out, int out_size)
{
    const float* x     = (const float*)d_in[0];
    const float* pairW = (const float*)d_in[1];
    const float* Y     = (const float*)d_in[2];
    float* out         = (float*)d_out;

    const int batch = in_sizes[0] / DIM;   // 8192

    const int b_blocks = 4;
    const int b_tile = batch / b_blocks;                 // 2048
    const int groups = b_tile / (GSIZE * BSTEP);         // 2048 / 512 = 4

    cudaFuncSetAttribute(pair_bilinear_kernel,
                         cudaFuncAttributeMaxDynamicSharedMemorySize, SMEM_BYTES);

    dim3 grid(NPAIRS / P_TILE, b_blocks);   // (256, 4) = 1024 blocks
    pair_bilinear_kernel<<<grid, THREADS, SMEM_BYTES>>>(x, pairW, Y, out, b_tile, groups);
}